// round 14
// baseline (speedup 1.0000x reference)
#include <cuda_runtime.h>
#include <cuda_fp16.h>
#include <cstdint>
#include <math.h>

#define NB 16
#define CI 512
#define CO 512
#define RES 64
#define OS 64
#define NT 1089      // 33x33 winograd tiles
#define NTP 1152     // padded tiles (9*128)

// ---------------- scratch (device globals) ----------------
__device__ float g_styles[NB * CI];
__device__ float g_s[NB * CI];
__device__ float g_ssum16[NB];
__device__ float g_q[CO * CI];
__device__ float g_d[NB * CO];
__device__ __half g_wt16[16 * CO * CI];                  // [comp][oc][ci]  8.4MB
__device__ __half g_xt[(size_t)NB * 16 * NTP * CI];      // [n][comp][tile][ci] 302MB
__device__ __half g_m16[(size_t)NB * CO * 16 * NTP];     // [n][oc][comp][tile] 302MB

// ---------------- helpers ----------------
__device__ __forceinline__ uint32_t smem_u32(const void* p) {
    uint32_t a;
    asm("{ .reg .u64 t; cvta.to.shared.u64 t, %1; cvt.u32.u64 %0, t; }" : "=r"(a) : "l"(p));
    return a;
}
__device__ __forceinline__ void cp16(uint32_t dst, const void* src) {
    asm volatile("cp.async.cg.shared.global [%0], [%1], 16;" :: "r"(dst), "l"(src));
}
__device__ __forceinline__ void ldsm4(uint32_t* r, uint32_t addr) {
    asm volatile("ldmatrix.sync.aligned.m8n8.x4.shared.b16 {%0,%1,%2,%3}, [%4];"
                 : "=r"(r[0]), "=r"(r[1]), "=r"(r[2]), "=r"(r[3]) : "r"(addr));
}
__device__ __forceinline__ void mma16816(float* c, const uint32_t* a, uint32_t b0, uint32_t b1) {
    asm volatile(
        "mma.sync.aligned.m16n8k16.row.col.f32.f16.f16.f32 "
        "{%0,%1,%2,%3}, {%4,%5,%6,%7}, {%8,%9}, {%0,%1,%2,%3};"
        : "+f"(c[0]), "+f"(c[1]), "+f"(c[2]), "+f"(c[3])
        : "r"(a[0]), "r"(a[1]), "r"(a[2]), "r"(a[3]), "r"(b0), "r"(b1));
}

// ---------------- setup kernels ----------------
__global__ void k_styles(const float* __restrict__ w,
                         const float* __restrict__ aw,
                         const float* __restrict__ ab) {
    int n = blockIdx.x, c = threadIdx.x;
    const float* wr = w + n * 512;
    const float* ar = aw + c * 512;
    float acc = 0.f;
    #pragma unroll 8
    for (int k = 0; k < 512; k++) acc += wr[k] * ar[k];
    float st = acc * 0.044194173824159216f + ab[c];
    g_styles[n * CI + c] = st;
    float v = st * st;
    #pragma unroll
    for (int off = 16; off; off >>= 1) v += __shfl_down_sync(0xffffffffu, v, off);
    __shared__ float ps[16];
    if ((c & 31) == 0) ps[c >> 5] = v;
    __syncthreads();
    if (c == 0) {
        float tot = 0.f;
        #pragma unroll
        for (int k = 0; k < 16; k++) tot += ps[k];
        g_ssum16[n] = tot;
    }
}

__global__ void k_norm_s() {
    int i = blockIdx.x * 512 + threadIdx.x;
    float tot = 0.f;
    #pragma unroll
    for (int k = 0; k < NB; k++) tot += g_ssum16[k];
    float msr = rsqrtf(tot * (1.0f / (NB * CI)));
    g_s[i] = g_styles[i] * msr;
}

// normalize weights, Winograd-transform to fp16 [comp][oc][ci], compute q
__global__ void k_wt(const float* __restrict__ cw) {
    int o = blockIdx.x, i = threadIdx.x;
    float g9[9]; float ss = 0.f;
    const float* p = cw + (o * CI + i) * 9;
    #pragma unroll
    for (int k = 0; k < 9; k++) { g9[k] = p[k]; ss += g9[k] * g9[k]; }
    __shared__ float red[512];
    red[i] = ss;
    __syncthreads();
    for (int s = 256; s; s >>= 1) { if (i < s) red[i] += red[i + s]; __syncthreads(); }
    float inv = rsqrtf(red[0] * (1.0f / 4608.0f));
    float g[3][3];
    #pragma unroll
    for (int k = 0; k < 9; k++) g[k / 3][k % 3] = g9[k] * inv;
    float r[4][3];
    #pragma unroll
    for (int j = 0; j < 3; j++) {
        r[0][j] = g[0][j];
        r[1][j] = 0.5f * (g[0][j] + g[1][j] + g[2][j]);
        r[2][j] = 0.5f * (g[0][j] - g[1][j] + g[2][j]);
        r[3][j] = g[2][j];
    }
    #pragma unroll
    for (int u = 0; u < 4; u++) {
        float gt0 = r[u][0];
        float gt1 = 0.5f * (r[u][0] + r[u][1] + r[u][2]);
        float gt2 = 0.5f * (r[u][0] - r[u][1] + r[u][2]);
        float gt3 = r[u][2];
        g_wt16[((u * 4 + 0) * 512 + o) * 512 + i] = __float2half_rn(gt0);
        g_wt16[((u * 4 + 1) * 512 + o) * 512 + i] = __float2half_rn(gt1);
        g_wt16[((u * 4 + 2) * 512 + o) * 512 + i] = __float2half_rn(gt2);
        g_wt16[((u * 4 + 3) * 512 + o) * 512 + i] = __float2half_rn(gt3);
    }
    g_q[o * CI + i] = ss * inv * inv;
}

// warp-per-(n,o) demod
__global__ void k_d() {
    int gw = blockIdx.x * 8 + (threadIdx.x >> 5);
    int lane = threadIdx.x & 31;
    int n = gw & 15, o = gw >> 4;
    const float* sp = g_s + n * CI;
    const float* qp = g_q + o * CI;
    float acc = 0.f;
    #pragma unroll 4
    for (int i = lane; i < 512; i += 32) { float sv = sp[i]; acc += sv * sv * qp[i]; }
    #pragma unroll
    for (int off = 16; off; off >>= 1) acc += __shfl_down_sync(0xffffffffu, acc, off);
    if (lane == 0) g_d[n * CO + o] = rsqrtf(acc + 1e-8f);
}

// ---------------- input transform: modulate, pad, B^T d B -> fp16 [n][comp][tile][ci]
#define XT_SMEM (4 * 68 * 65 * 4)
__global__ void __launch_bounds__(256, 2) k_xtrans(const float* __restrict__ x) {
    extern __shared__ float s[];   // [i 4][col 68][ci 64] stride 65
    int ty = blockIdx.x;   // 0..32
    int n  = blockIdx.y;
    int t  = threadIdx.x;
    const float* sp = g_s + n * 512;

    for (int ic0 = 0; ic0 < 512; ic0 += 64) {
        __syncthreads();
        for (int e = t; e < 4 * 68 * 64; e += 256) {
            int col = e % 68; int rest = e / 68;
            int i = rest & 3, ci = rest >> 2;
            int xr = 2 * ty + i - 2, xc = col - 2;
            float v = 0.f;
            if (xr >= 0 && xr < 64 && xc >= 0 && xc < 64)
                v = x[(((size_t)n * 512 + ic0 + ci) * 64 + xr) * 64 + xc] * sp[ic0 + ci];
            s[(i * 68 + col) * 65 + ci] = v;
        }
        __syncthreads();
        int ci = t & 63, txi = t >> 6;
        for (int pss = 0; pss < 9; pss++) {
            int tx = pss * 4 + txi;
            if (tx < 33) {
                float d[4][4];
                #pragma unroll
                for (int i = 0; i < 4; i++)
                    #pragma unroll
                    for (int j = 0; j < 4; j++)
                        d[i][j] = s[(i * 68 + 2 * tx + j) * 65 + ci];
                float tr[4][4];
                #pragma unroll
                for (int j = 0; j < 4; j++) {
                    tr[0][j] = d[0][j] - d[2][j];
                    tr[1][j] = d[1][j] + d[2][j];
                    tr[2][j] = d[2][j] - d[1][j];
                    tr[3][j] = d[1][j] - d[3][j];
                }
                int tile = ty * 33 + tx;
                #pragma unroll
                for (int u = 0; u < 4; u++) {
                    float d0 = tr[u][0] - tr[u][2];
                    float d1 = tr[u][1] + tr[u][2];
                    float d2 = tr[u][2] - tr[u][1];
                    float d3 = tr[u][1] - tr[u][3];
                    size_t b0 = ((size_t)((n * 16 + u * 4 + 0)) * NTP + tile) * 512 + ic0 + ci;
                    size_t b1 = ((size_t)((n * 16 + u * 4 + 1)) * NTP + tile) * 512 + ic0 + ci;
                    size_t b2 = ((size_t)((n * 16 + u * 4 + 2)) * NTP + tile) * 512 + ic0 + ci;
                    size_t b3 = ((size_t)((n * 16 + u * 4 + 3)) * NTP + tile) * 512 + ic0 + ci;
                    g_xt[b0] = __float2half_rn(d0);
                    g_xt[b1] = __float2half_rn(d1);
                    g_xt[b2] = __float2half_rn(d2);
                    g_xt[b3] = __float2half_rn(d3);
                }
            }
        }
    }
}

// ---------------- winograd GEMM: per comp, M[n][oc][comp][tile] fp16 ----------------
#define ROWB 144
#define TILEB 18432
#define STAGEB 36864
#define CONV_SMEM (2 * STAGEB)

__global__ void __launch_bounds__(256, 2) k_conv() {
    extern __shared__ char smem[];
    uint32_t sb = smem_u32(smem);
    int t = threadIdx.x, wid = t >> 5, lane = t & 31;
    int wm = wid & 1, wn = wid >> 1;
    int oc0 = blockIdx.x * 128;
    int t0  = blockIdx.y * 128;
    int n   = blockIdx.z;

    auto stage_issue = [&](int it, int buf) {
        int comp = it >> 3, ch = it & 7;
        int ic0 = ch << 6;
        const __half* ah = g_wt16 + ((size_t)(comp * 512 + oc0)) * 512 + ic0;
        const __half* bh = g_xt + ((size_t)(n * 16 + comp) * NTP + t0) * 512 + ic0;
        uint32_t sbase = sb + buf * STAGEB;
        #pragma unroll
        for (int j = 0; j < 8; j++) {
            int id = j * 256 + t;
            int tile = id >> 10, e = id & 1023;
            int row = e >> 3, c16 = e & 7;
            const __half* src = tile ? bh : ah;
            cp16(sbase + tile * TILEB + row * ROWB + c16 * 16,
                 src + (size_t)row * 512 + c16 * 8);
        }
        asm volatile("cp.async.commit_group;" ::: "memory");
    };

    stage_issue(0, 0);

    int rl = lane & 15, chh = lane >> 4;
    int g4 = lane >> 2, t4 = lane & 3;
    __half* mbase = g_m16 + (((size_t)(n * 512 + oc0) * 16) * NTP + t0);

    for (int comp = 0; comp < 16; comp++) {
        float acc[4][4][4];
        #pragma unroll
        for (int mi = 0; mi < 4; mi++)
            #pragma unroll
            for (int ni = 0; ni < 4; ni++)
                #pragma unroll
                for (int q = 0; q < 4; q++) acc[mi][ni][q] = 0.f;

        #pragma unroll 1
        for (int ch = 0; ch < 8; ch++) {
            int it = comp * 8 + ch;
            int buf = it & 1;
            if (it + 1 < 128) {
                stage_issue(it + 1, buf ^ 1);
                asm volatile("cp.async.wait_group 1;" ::: "memory");
            } else {
                asm volatile("cp.async.wait_group 0;" ::: "memory");
            }
            __syncthreads();

            uint32_t At = sb + buf * STAGEB;
            uint32_t Bt = At + TILEB;
            #pragma unroll
            for (int kk = 0; kk < 4; kk++) {
                uint32_t kb = (kk * 2 + chh) * 16;
                uint32_t a[4][4], b[2][4];
                #pragma unroll
                for (int nj = 0; nj < 2; nj++)
                    ldsm4(b[nj], Bt + (wn * 32 + nj * 16 + rl) * ROWB + kb);
                #pragma unroll
                for (int mi = 0; mi < 4; mi++)
                    ldsm4(a[mi], At + (wm * 64 + mi * 16 + rl) * ROWB + kb);
                #pragma unroll
                for (int mi = 0; mi < 4; mi++)
                    #pragma unroll
                    for (int ni = 0; ni < 4; ni++) {
                        int nj = ni >> 1, sub = ni & 1;
                        mma16816(acc[mi][ni], a[mi], b[nj][sub], b[nj][sub + 2]);
                    }
            }
            __syncthreads();
        }

        __half* mc = mbase + (size_t)comp * NTP;
        #pragma unroll
        for (int mi = 0; mi < 4; mi++) {
            int oa = wm * 64 + mi * 16 + g4;
            __half* pa = mc + (size_t)oa * 16 * NTP;
            __half* pb = mc + (size_t)(oa + 8) * 16 * NTP;
            #pragma unroll
            for (int ni = 0; ni < 4; ni++) {
                int px = wn * 32 + ni * 8 + t4 * 2;
                __half2 va = __floats2half2_rn(acc[mi][ni][0], acc[mi][ni][1]);
                __half2 vb = __floats2half2_rn(acc[mi][ni][2], acc[mi][ni][3]);
                *(__half2*)(pa + px) = va;
                *(__half2*)(pb + px) = vb;
            }
        }
    }
}

// ---------------- fused output-transform + filtered_lrelu: one CTA per (n,oc) ----------------
#define F_SY 0
#define F_SUV 5032
#define F_SU 15520
#define F_SDV 21358
#define FIR_SMEM (23582 * 4)
#define LRC1 5.656854249492381f
#define LRC2 1.1313708498984762f

__global__ void __launch_bounds__(256, 2) k_fir(const float* __restrict__ fu,
                                                const float* __restrict__ fd,
                                                const float* __restrict__ cb,
                                                float* __restrict__ out) {
    extern __shared__ float sm[];
    float* sY  = sm + F_SY;
    float* sUV = sm + F_SUV;
    float* sU  = sm + F_SU;
    float* sDV = sm + F_SDV;
    int t = threadIdx.x;
    int nc = blockIdx.x;            // n*512 + oc
    int oc = nc & 511;

    float fe[6], fo[6], fdr[12];
    #pragma unroll
    for (int j = 0; j < 6; j++) { fe[j] = fu[2 * j]; fo[j] = fu[2 * j + 1]; }
    #pragma unroll
    for (int j = 0; j < 12; j++) fdr[j] = fd[j];

    float4* sY4 = (float4*)sY;
    float4 z4 = make_float4(0.f, 0.f, 0.f, 0.f);
    for (int e = t; e < 1258; e += 256) sY4[e] = z4;
    for (int e = t; e < 138 * 8; e += 256) {
        int r = e >> 3, c = e & 7;
        sUV[r * 76 + ((c < 4) ? c : (66 + c))] = 0.f;
    }
    __syncthreads();

    // output transform from fp16 m
    {
        const __half* mb = g_m16 + ((size_t)nc * 16) * NTP;
        float dd = g_d[nc];
        float bias = cb[oc];
        for (int tile = t; tile < NT; tile += 256) {
            float m[16];
            #pragma unroll
            for (int c = 0; c < 16; c++) m[c] = __half2float(mb[(size_t)c * NTP + tile]);
            float s0[4], s1[4];
            #pragma unroll
            for (int v = 0; v < 4; v++) {
                s0[v] = m[v] + m[4 + v] + m[8 + v];
                s1[v] = m[4 + v] - m[8 + v] - m[12 + v];
            }
            float y00 = s0[0] + s0[1] + s0[2], y01 = s0[1] - s0[2] - s0[3];
            float y10 = s1[0] + s1[1] + s1[2], y11 = s1[1] - s1[2] - s1[3];
            int ty = tile / 33, tx = tile - ty * 33;
            int off = (4 + 2 * ty) * 68 + 2 * tx;
            sY[off]      = y00 * dd + bias;
            sY[off + 1]  = y01 * dd + bias;
            sY[off + 68] = y10 * dd + bias;
            sY[off + 69] = y11 * dd + bias;
        }
    }
    __syncthreads();

    for (int e = t; e < 69 * 66; e += 256) {
        int q = e / 66, xx = e - q * 66;
        const float* src = sY + q * 68 + xx;
        float ve = 0.f, vo = 0.f;
        #pragma unroll
        for (int j = 0; j < 6; j++) {
            float s = src[j * 68];
            ve += fo[j] * s;
            vo += fe[j] * s;
        }
        sUV[(2 * q) * 76 + 4 + xx] = ve;
        sUV[(2 * q + 1) * 76 + 4 + xx] = vo;
    }
    __syncthreads();

    for (int oy0 = 0; oy0 < 64; oy0 += 16) {
        for (int e = t; e < 42 * 69; e += 256) {
            int rr = e / 69, q = e - rr * 69;
            const float* src = sUV + (2 * oy0 + rr) * 76 + q;
            float ve = 0.f, vo = 0.f;
            #pragma unroll
            for (int j = 0; j < 6; j++) {
                float s = src[j];
                ve += fo[j] * s;
                vo += fe[j] * s;
            }
            float w0 = fminf(fmaxf(fmaxf(ve * LRC1, ve * LRC2), -256.f), 256.f);
            float w1 = fminf(fmaxf(fmaxf(vo * LRC1, vo * LRC2), -256.f), 256.f);
            sU[rr * 139 + 2 * q] = w0;
            sU[rr * 139 + 2 * q + 1] = w1;
        }
        __syncthreads();
        for (int e = t; e < 16 * 138; e += 256) {
            int yy = e / 138, c = e - yy * 138;
            const float* src = sU + 2 * yy * 139 + c;
            float acc = 0.f;
            #pragma unroll
            for (int tp = 0; tp < 12; tp++) acc += fdr[tp] * src[tp * 139];
            sDV[yy * 139 + c] = acc;
        }
        __syncthreads();
        for (int e = t; e < 16 * 64; e += 256) {
            int yy = e >> 6, ox = e & 63;
            const float* src = sDV + yy * 139 + 2 * ox;
            float acc = 0.f;
            #pragma unroll
            for (int tp = 0; tp < 12; tp++) acc += fdr[tp] * src[tp];
            out[(size_t)nc * 4096 + (oy0 + yy) * 64 + ox] = acc;
        }
        __syncthreads();
    }
}

// ---------------- launch ----------------
extern "C" void kernel_launch(void* const* d_in, const int* in_sizes, int n_in,
                              void* d_out, int out_size) {
    const float* x  = (const float*)d_in[0];
    const float* w  = (const float*)d_in[1];
    const float* aw = (const float*)d_in[2];
    const float* ab = (const float*)d_in[3];
    const float* cw = (const float*)d_in[4];
    const float* cb = (const float*)d_in[5];
    const float* fu = (const float*)d_in[6];
    const float* fd = (const float*)d_in[7];
    float* out = (float*)d_out;

    cudaFuncSetAttribute(k_conv,   cudaFuncAttributeMaxDynamicSharedMemorySize, CONV_SMEM);
    cudaFuncSetAttribute(k_fir,    cudaFuncAttributeMaxDynamicSharedMemorySize, FIR_SMEM);
    cudaFuncSetAttribute(k_xtrans, cudaFuncAttributeMaxDynamicSharedMemorySize, XT_SMEM);

    k_styles<<<NB, 512>>>(w, aw, ab);
    k_norm_s<<<NB, 512>>>();
    k_wt<<<CO, 512>>>(cw);
    k_d<<<1024, 256>>>();
    k_xtrans<<<dim3(33, NB), 256, XT_SMEM>>>(x);

    k_conv<<<dim3(4, 9, NB), 256, CONV_SMEM>>>();

    k_fir<<<NB * CO, 256, FIR_SMEM>>>(fu, fd, cb, out);
}

// round 15
// speedup vs baseline: 1.0492x; 1.0492x over previous
#include <cuda_runtime.h>
#include <cuda_fp16.h>
#include <cstdint>
#include <math.h>

#define NB 16
#define CI 512
#define CO 512
#define RES 64
#define OS 64
#define NT 1089      // 33x33 winograd tiles
#define NTP 1152     // padded tiles (9*128)

// ---------------- scratch (device globals) ----------------
__device__ float g_styles[NB * CI];
__device__ float g_s[NB * CI];
__device__ float g_ssum16[NB];
__device__ float g_q[CO * CI];
__device__ float g_d[NB * CO];
__device__ __half g_wt16[16 * CO * CI];                  // [comp][oc][ci]  8.4MB
__device__ __half g_xt[(size_t)NB * 16 * NTP * CI];      // [n][comp][tile][ci] 302MB
__device__ float  g_m[(size_t)NB * CO * 16 * NTP];       // [n][oc][comp][tile] 604MB

// ---------------- helpers ----------------
__device__ __forceinline__ uint32_t smem_u32(const void* p) {
    uint32_t a;
    asm("{ .reg .u64 t; cvta.to.shared.u64 t, %1; cvt.u32.u64 %0, t; }" : "=r"(a) : "l"(p));
    return a;
}
__device__ __forceinline__ void cp16(uint32_t dst, const void* src) {
    asm volatile("cp.async.cg.shared.global [%0], [%1], 16;" :: "r"(dst), "l"(src));
}
__device__ __forceinline__ void ldsm4(uint32_t* r, uint32_t addr) {
    asm volatile("ldmatrix.sync.aligned.m8n8.x4.shared.b16 {%0,%1,%2,%3}, [%4];"
                 : "=r"(r[0]), "=r"(r[1]), "=r"(r[2]), "=r"(r[3]) : "r"(addr));
}
__device__ __forceinline__ void mma16816(float* c, const uint32_t* a, uint32_t b0, uint32_t b1) {
    asm volatile(
        "mma.sync.aligned.m16n8k16.row.col.f32.f16.f16.f32 "
        "{%0,%1,%2,%3}, {%4,%5,%6,%7}, {%8,%9}, {%0,%1,%2,%3};"
        : "+f"(c[0]), "+f"(c[1]), "+f"(c[2]), "+f"(c[3])
        : "r"(a[0]), "r"(a[1]), "r"(a[2]), "r"(a[3]), "r"(b0), "r"(b1));
}

// ---------------- setup kernels ----------------
__global__ void k_styles(const float* __restrict__ w,
                         const float* __restrict__ aw,
                         const float* __restrict__ ab) {
    int n = blockIdx.x, c = threadIdx.x;
    const float* wr = w + n * 512;
    const float* ar = aw + c * 512;
    float acc = 0.f;
    #pragma unroll 8
    for (int k = 0; k < 512; k++) acc += wr[k] * ar[k];
    float st = acc * 0.044194173824159216f + ab[c];
    g_styles[n * CI + c] = st;
    float v = st * st;
    #pragma unroll
    for (int off = 16; off; off >>= 1) v += __shfl_down_sync(0xffffffffu, v, off);
    __shared__ float ps[16];
    if ((c & 31) == 0) ps[c >> 5] = v;
    __syncthreads();
    if (c == 0) {
        float tot = 0.f;
        #pragma unroll
        for (int k = 0; k < 16; k++) tot += ps[k];
        g_ssum16[n] = tot;
    }
}

__global__ void k_norm_s() {
    int i = blockIdx.x * 512 + threadIdx.x;
    float tot = 0.f;
    #pragma unroll
    for (int k = 0; k < NB; k++) tot += g_ssum16[k];
    float msr = rsqrtf(tot * (1.0f / (NB * CI)));
    g_s[i] = g_styles[i] * msr;
}

// normalize weights, Winograd-transform to fp16 [comp][oc][ci], compute q
__global__ void k_wt(const float* __restrict__ cw) {
    int o = blockIdx.x, i = threadIdx.x;
    float g9[9]; float ss = 0.f;
    const float* p = cw + (o * CI + i) * 9;
    #pragma unroll
    for (int k = 0; k < 9; k++) { g9[k] = p[k]; ss += g9[k] * g9[k]; }
    __shared__ float red[512];
    red[i] = ss;
    __syncthreads();
    for (int s = 256; s; s >>= 1) { if (i < s) red[i] += red[i + s]; __syncthreads(); }
    float inv = rsqrtf(red[0] * (1.0f / 4608.0f));
    float g[3][3];
    #pragma unroll
    for (int k = 0; k < 9; k++) g[k / 3][k % 3] = g9[k] * inv;
    float r[4][3];
    #pragma unroll
    for (int j = 0; j < 3; j++) {
        r[0][j] = g[0][j];
        r[1][j] = 0.5f * (g[0][j] + g[1][j] + g[2][j]);
        r[2][j] = 0.5f * (g[0][j] - g[1][j] + g[2][j]);
        r[3][j] = g[2][j];
    }
    #pragma unroll
    for (int u = 0; u < 4; u++) {
        float gt0 = r[u][0];
        float gt1 = 0.5f * (r[u][0] + r[u][1] + r[u][2]);
        float gt2 = 0.5f * (r[u][0] - r[u][1] + r[u][2]);
        float gt3 = r[u][2];
        g_wt16[((u * 4 + 0) * 512 + o) * 512 + i] = __float2half_rn(gt0);
        g_wt16[((u * 4 + 1) * 512 + o) * 512 + i] = __float2half_rn(gt1);
        g_wt16[((u * 4 + 2) * 512 + o) * 512 + i] = __float2half_rn(gt2);
        g_wt16[((u * 4 + 3) * 512 + o) * 512 + i] = __float2half_rn(gt3);
    }
    g_q[o * CI + i] = ss * inv * inv;
}

// warp-per-(n,o) demod
__global__ void k_d() {
    int gw = blockIdx.x * 8 + (threadIdx.x >> 5);
    int lane = threadIdx.x & 31;
    int n = gw & 15, o = gw >> 4;
    const float* sp = g_s + n * CI;
    const float* qp = g_q + o * CI;
    float acc = 0.f;
    #pragma unroll 4
    for (int i = lane; i < 512; i += 32) { float sv = sp[i]; acc += sv * sv * qp[i]; }
    #pragma unroll
    for (int off = 16; off; off >>= 1) acc += __shfl_down_sync(0xffffffffu, acc, off);
    if (lane == 0) g_d[n * CO + o] = rsqrtf(acc + 1e-8f);
}

// ---------------- input transform: modulate, pad, B^T d B -> fp16 [n][comp][tile][ci]
#define XT_SMEM (4 * 68 * 65 * 4)
__global__ void __launch_bounds__(256, 2) k_xtrans(const float* __restrict__ x) {
    extern __shared__ float s[];   // [i 4][col 68][ci 64] stride 65
    int ty = blockIdx.x;   // 0..32
    int n  = blockIdx.y;
    int t  = threadIdx.x;
    const float* sp = g_s + n * 512;

    for (int ic0 = 0; ic0 < 512; ic0 += 64) {
        __syncthreads();
        for (int e = t; e < 4 * 68 * 64; e += 256) {
            int col = e % 68; int rest = e / 68;
            int i = rest & 3, ci = rest >> 2;
            int xr = 2 * ty + i - 2, xc = col - 2;
            float v = 0.f;
            if (xr >= 0 && xr < 64 && xc >= 0 && xc < 64)
                v = x[(((size_t)n * 512 + ic0 + ci) * 64 + xr) * 64 + xc] * sp[ic0 + ci];
            s[(i * 68 + col) * 65 + ci] = v;
        }
        __syncthreads();
        int ci = t & 63, txi = t >> 6;
        for (int pss = 0; pss < 9; pss++) {
            int tx = pss * 4 + txi;
            if (tx < 33) {
                float d[4][4];
                #pragma unroll
                for (int i = 0; i < 4; i++)
                    #pragma unroll
                    for (int j = 0; j < 4; j++)
                        d[i][j] = s[(i * 68 + 2 * tx + j) * 65 + ci];
                float tr[4][4];
                #pragma unroll
                for (int j = 0; j < 4; j++) {
                    tr[0][j] = d[0][j] - d[2][j];
                    tr[1][j] = d[1][j] + d[2][j];
                    tr[2][j] = d[2][j] - d[1][j];
                    tr[3][j] = d[1][j] - d[3][j];
                }
                int tile = ty * 33 + tx;
                #pragma unroll
                for (int u = 0; u < 4; u++) {
                    float d0 = tr[u][0] - tr[u][2];
                    float d1 = tr[u][1] + tr[u][2];
                    float d2 = tr[u][2] - tr[u][1];
                    float d3 = tr[u][1] - tr[u][3];
                    size_t b0 = ((size_t)((n * 16 + u * 4 + 0)) * NTP + tile) * 512 + ic0 + ci;
                    size_t b1 = ((size_t)((n * 16 + u * 4 + 1)) * NTP + tile) * 512 + ic0 + ci;
                    size_t b2 = ((size_t)((n * 16 + u * 4 + 2)) * NTP + tile) * 512 + ic0 + ci;
                    size_t b3 = ((size_t)((n * 16 + u * 4 + 3)) * NTP + tile) * 512 + ic0 + ci;
                    g_xt[b0] = __float2half_rn(d0);
                    g_xt[b1] = __float2half_rn(d1);
                    g_xt[b2] = __float2half_rn(d2);
                    g_xt[b3] = __float2half_rn(d3);
                }
            }
        }
    }
}

// ---------------- winograd GEMM: per comp, M[n][oc][comp][tile] fp32 ----------------
#define ROWB 144
#define TILEB 18432
#define STAGEB 36864
#define CONV_SMEM (2 * STAGEB)

__global__ void __launch_bounds__(256, 2) k_conv() {
    extern __shared__ char smem[];
    uint32_t sb = smem_u32(smem);
    int t = threadIdx.x, wid = t >> 5, lane = t & 31;
    int wm = wid & 1, wn = wid >> 1;
    int oc0 = blockIdx.x * 128;
    int t0  = blockIdx.y * 128;
    int n   = blockIdx.z;

    auto stage_issue = [&](int it, int buf) {
        int comp = it >> 3, ch = it & 7;
        int ic0 = ch << 6;
        const __half* ah = g_wt16 + ((size_t)(comp * 512 + oc0)) * 512 + ic0;
        const __half* bh = g_xt + ((size_t)(n * 16 + comp) * NTP + t0) * 512 + ic0;
        uint32_t sbase = sb + buf * STAGEB;
        #pragma unroll
        for (int j = 0; j < 8; j++) {
            int id = j * 256 + t;
            int tile = id >> 10, e = id & 1023;
            int row = e >> 3, c16 = e & 7;
            const __half* src = tile ? bh : ah;
            cp16(sbase + tile * TILEB + row * ROWB + c16 * 16,
                 src + (size_t)row * 512 + c16 * 8);
        }
        asm volatile("cp.async.commit_group;" ::: "memory");
    };

    stage_issue(0, 0);

    int rl = lane & 15, chh = lane >> 4;
    int g4 = lane >> 2, t4 = lane & 3;
    float* mbase = g_m + (((size_t)(n * 512 + oc0) * 16) * NTP + t0);

    for (int comp = 0; comp < 16; comp++) {
        float acc[4][4][4];
        #pragma unroll
        for (int mi = 0; mi < 4; mi++)
            #pragma unroll
            for (int ni = 0; ni < 4; ni++)
                #pragma unroll
                for (int q = 0; q < 4; q++) acc[mi][ni][q] = 0.f;

        #pragma unroll 1
        for (int ch = 0; ch < 8; ch++) {
            int it = comp * 8 + ch;
            int buf = it & 1;
            if (it + 1 < 128) {
                stage_issue(it + 1, buf ^ 1);
                asm volatile("cp.async.wait_group 1;" ::: "memory");
            } else {
                asm volatile("cp.async.wait_group 0;" ::: "memory");
            }
            __syncthreads();

            uint32_t At = sb + buf * STAGEB;
            uint32_t Bt = At + TILEB;
            #pragma unroll
            for (int kk = 0; kk < 4; kk++) {
                uint32_t kb = (kk * 2 + chh) * 16;
                uint32_t a[4][4], b[2][4];
                #pragma unroll
                for (int nj = 0; nj < 2; nj++)
                    ldsm4(b[nj], Bt + (wn * 32 + nj * 16 + rl) * ROWB + kb);
                #pragma unroll
                for (int mi = 0; mi < 4; mi++)
                    ldsm4(a[mi], At + (wm * 64 + mi * 16 + rl) * ROWB + kb);
                #pragma unroll
                for (int mi = 0; mi < 4; mi++)
                    #pragma unroll
                    for (int ni = 0; ni < 4; ni++) {
                        int nj = ni >> 1, sub = ni & 1;
                        mma16816(acc[mi][ni], a[mi], b[nj][sub], b[nj][sub + 2]);
                    }
            }
            __syncthreads();
        }

        float* mc = mbase + (size_t)comp * NTP;
        #pragma unroll
        for (int mi = 0; mi < 4; mi++) {
            int oa = wm * 64 + mi * 16 + g4;
            float* pa = mc + (size_t)oa * 16 * NTP;
            float* pb = mc + (size_t)(oa + 8) * 16 * NTP;
            #pragma unroll
            for (int ni = 0; ni < 4; ni++) {
                int px = wn * 32 + ni * 8 + t4 * 2;
                float2 va, vb;
                va.x = acc[mi][ni][0]; va.y = acc[mi][ni][1];
                vb.x = acc[mi][ni][2]; vb.y = acc[mi][ni][3];
                *(float2*)(pa + px) = va;
                *(float2*)(pb + px) = vb;
            }
        }
    }
}

// ---------------- fused output-transform + filtered_lrelu: one CTA per (n,oc) ----------------
#define F_SY 0
#define F_SUV 5032
#define F_SU 15520
#define F_SDV 21358
#define FIR_SMEM (23582 * 4)
#define LRC1 5.656854249492381f
#define LRC2 1.1313708498984762f

__global__ void __launch_bounds__(256, 2) k_fir(const float* __restrict__ fu,
                                                const float* __restrict__ fd,
                                                const float* __restrict__ cb,
                                                float* __restrict__ out) {
    extern __shared__ float sm[];
    float* sY  = sm + F_SY;
    float* sUV = sm + F_SUV;
    float* sU  = sm + F_SU;
    float* sDV = sm + F_SDV;
    int t = threadIdx.x;
    int nc = blockIdx.x;            // n*512 + oc
    int oc = nc & 511;

    float fe[6], fo[6], fdr[12];
    #pragma unroll
    for (int j = 0; j < 6; j++) { fe[j] = fu[2 * j]; fo[j] = fu[2 * j + 1]; }
    #pragma unroll
    for (int j = 0; j < 12; j++) fdr[j] = fd[j];

    float4* sY4 = (float4*)sY;
    float4 z4 = make_float4(0.f, 0.f, 0.f, 0.f);
    for (int e = t; e < 1258; e += 256) sY4[e] = z4;
    for (int e = t; e < 138 * 8; e += 256) {
        int r = e >> 3, c = e & 7;
        sUV[r * 76 + ((c < 4) ? c : (66 + c))] = 0.f;
    }
    __syncthreads();

    // output transform from fp32 m: m[16] -> 2x2 pixels, demod + bias
    {
        const float* mb = g_m + ((size_t)nc * 16) * NTP;
        float dd = g_d[nc];
        float bias = cb[oc];
        for (int tile = t; tile < NT; tile += 256) {
            float m[16];
            #pragma unroll
            for (int c = 0; c < 16; c++) m[c] = mb[(size_t)c * NTP + tile];
            float s0[4], s1[4];
            #pragma unroll
            for (int v = 0; v < 4; v++) {
                s0[v] = m[v] + m[4 + v] + m[8 + v];
                s1[v] = m[4 + v] - m[8 + v] - m[12 + v];
            }
            float y00 = s0[0] + s0[1] + s0[2], y01 = s0[1] - s0[2] - s0[3];
            float y10 = s1[0] + s1[1] + s1[2], y11 = s1[1] - s1[2] - s1[3];
            int ty = tile / 33, tx = tile - ty * 33;
            int off = (4 + 2 * ty) * 68 + 2 * tx;
            sY[off]      = y00 * dd + bias;
            sY[off + 1]  = y01 * dd + bias;
            sY[off + 68] = y10 * dd + bias;
            sY[off + 69] = y11 * dd + bias;
        }
    }
    __syncthreads();

    // up-vertical, paired parity
    for (int e = t; e < 69 * 66; e += 256) {
        int q = e / 66, xx = e - q * 66;
        const float* src = sY + q * 68 + xx;
        float ve = 0.f, vo = 0.f;
        #pragma unroll
        for (int j = 0; j < 6; j++) {
            float s = src[j * 68];
            ve += fo[j] * s;
            vo += fe[j] * s;
        }
        sUV[(2 * q) * 76 + 4 + xx] = ve;
        sUV[(2 * q + 1) * 76 + 4 + xx] = vo;
    }
    __syncthreads();

    for (int oy0 = 0; oy0 < 64; oy0 += 16) {
        // up-horizontal + lrelu + clamp (paired parity)
        for (int e = t; e < 42 * 69; e += 256) {
            int rr = e / 69, q = e - rr * 69;
            const float* src = sUV + (2 * oy0 + rr) * 76 + q;
            float ve = 0.f, vo = 0.f;
            #pragma unroll
            for (int j = 0; j < 6; j++) {
                float s = src[j];
                ve += fo[j] * s;
                vo += fe[j] * s;
            }
            float w0 = fminf(fmaxf(fmaxf(ve * LRC1, ve * LRC2), -256.f), 256.f);
            float w1 = fminf(fmaxf(fmaxf(vo * LRC1, vo * LRC2), -256.f), 256.f);
            sU[rr * 139 + 2 * q] = w0;
            sU[rr * 139 + 2 * q + 1] = w1;
        }
        __syncthreads();
        // down-vertical, 4-way register-blocked (18 loads -> 4 outputs)
        for (int e = t; e < 4 * 138; e += 256) {
            int c = e % 138, g = e / 138;
            const float* src = sU + (8 * g) * 139 + c;
            float r[18];
            #pragma unroll
            for (int j = 0; j < 18; j++) r[j] = src[j * 139];
            #pragma unroll
            for (int j = 0; j < 4; j++) {
                float acc = 0.f;
                #pragma unroll
                for (int tp = 0; tp < 12; tp++) acc += fdr[tp] * r[2 * j + tp];
                sDV[(4 * g + j) * 139 + c] = acc;
            }
        }
        __syncthreads();
        // down-horizontal, 4-way register-blocked -> float4 out
        {
            int yy = t & 15, oxg = t >> 4;   // 256 items exactly
            const float* src = sDV + yy * 139 + 8 * oxg;
            float r[18];
            #pragma unroll
            for (int j = 0; j < 18; j++) r[j] = src[j];
            float4 o4;
            float* op = (float*)&o4;
            #pragma unroll
            for (int j = 0; j < 4; j++) {
                float acc = 0.f;
                #pragma unroll
                for (int tp = 0; tp < 12; tp++) acc += fdr[tp] * r[2 * j + tp];
                op[j] = acc;
            }
            *(float4*)(out + (size_t)nc * 4096 + (oy0 + yy) * 64 + 4 * oxg) = o4;
        }
        __syncthreads();
    }
}

// ---------------- launch ----------------
extern "C" void kernel_launch(void* const* d_in, const int* in_sizes, int n_in,
                              void* d_out, int out_size) {
    const float* x  = (const float*)d_in[0];
    const float* w  = (const float*)d_in[1];
    const float* aw = (const float*)d_in[2];
    const float* ab = (const float*)d_in[3];
    const float* cw = (const float*)d_in[4];
    const float* cb = (const float*)d_in[5];
    const float* fu = (const float*)d_in[6];
    const float* fd = (const float*)d_in[7];
    float* out = (float*)d_out;

    cudaFuncSetAttribute(k_conv,   cudaFuncAttributeMaxDynamicSharedMemorySize, CONV_SMEM);
    cudaFuncSetAttribute(k_fir,    cudaFuncAttributeMaxDynamicSharedMemorySize, FIR_SMEM);
    cudaFuncSetAttribute(k_xtrans, cudaFuncAttributeMaxDynamicSharedMemorySize, XT_SMEM);

    k_styles<<<NB, 512>>>(w, aw, ab);
    k_norm_s<<<NB, 512>>>();
    k_wt<<<CO, 512>>>(cw);
    k_d<<<1024, 256>>>();
    k_xtrans<<<dim3(33, NB), 256, XT_SMEM>>>(x);

    k_conv<<<dim3(4, 9, NB), 256, CONV_SMEM>>>();

    k_fir<<<NB * CO, 256, FIR_SMEM>>>(fu, fd, cb, out);
}

// round 16
// speedup vs baseline: 1.0789x; 1.0283x over previous
#include <cuda_runtime.h>
#include <cuda_fp16.h>
#include <cstdint>
#include <math.h>

#define NB 16
#define CI 512
#define CO 512
#define RES 64
#define OS 64
#define NT 1089      // 33x33 winograd tiles
#define NTP 1152     // padded tiles (9*128)

// ---------------- scratch (device globals) ----------------
__device__ float g_styles[NB * CI];
__device__ float g_s[NB * CI];
__device__ float g_ssum16[NB];
__device__ float g_q[CO * CI];
__device__ float g_d[NB * CO];
__device__ __half g_wt16[16 * CO * CI];                  // [comp][oc][ci]  8.4MB
__device__ __half g_xt[(size_t)NB * 16 * NTP * CI];      // [n][comp][tile][ci] 302MB
__device__ float  g_m[(size_t)NB * CO * 16 * NTP];       // [n][oc][comp][tile] 604MB

// ---------------- helpers ----------------
__device__ __forceinline__ uint32_t smem_u32(const void* p) {
    uint32_t a;
    asm("{ .reg .u64 t; cvta.to.shared.u64 t, %1; cvt.u32.u64 %0, t; }" : "=r"(a) : "l"(p));
    return a;
}
__device__ __forceinline__ void cp16(uint32_t dst, const void* src) {
    asm volatile("cp.async.cg.shared.global [%0], [%1], 16;" :: "r"(dst), "l"(src));
}
__device__ __forceinline__ void ldsm4(uint32_t* r, uint32_t addr) {
    asm volatile("ldmatrix.sync.aligned.m8n8.x4.shared.b16 {%0,%1,%2,%3}, [%4];"
                 : "=r"(r[0]), "=r"(r[1]), "=r"(r[2]), "=r"(r[3]) : "r"(addr));
}
__device__ __forceinline__ void mma16816(float* c, const uint32_t* a, uint32_t b0, uint32_t b1) {
    asm volatile(
        "mma.sync.aligned.m16n8k16.row.col.f32.f16.f16.f32 "
        "{%0,%1,%2,%3}, {%4,%5,%6,%7}, {%8,%9}, {%0,%1,%2,%3};"
        : "+f"(c[0]), "+f"(c[1]), "+f"(c[2]), "+f"(c[3])
        : "r"(a[0]), "r"(a[1]), "r"(a[2]), "r"(a[3]), "r"(b0), "r"(b1));
}

// ---------------- setup kernels ----------------
__global__ void k_styles(const float* __restrict__ w,
                         const float* __restrict__ aw,
                         const float* __restrict__ ab) {
    int n = blockIdx.x, c = threadIdx.x;
    const float* wr = w + n * 512;
    const float* ar = aw + c * 512;
    float acc = 0.f;
    #pragma unroll 8
    for (int k = 0; k < 512; k++) acc += wr[k] * ar[k];
    float st = acc * 0.044194173824159216f + ab[c];
    g_styles[n * CI + c] = st;
    float v = st * st;
    #pragma unroll
    for (int off = 16; off; off >>= 1) v += __shfl_down_sync(0xffffffffu, v, off);
    __shared__ float ps[16];
    if ((c & 31) == 0) ps[c >> 5] = v;
    __syncthreads();
    if (c == 0) {
        float tot = 0.f;
        #pragma unroll
        for (int k = 0; k < 16; k++) tot += ps[k];
        g_ssum16[n] = tot;
    }
}

__global__ void k_norm_s() {
    int i = blockIdx.x * 512 + threadIdx.x;
    float tot = 0.f;
    #pragma unroll
    for (int k = 0; k < NB; k++) tot += g_ssum16[k];
    float msr = rsqrtf(tot * (1.0f / (NB * CI)));
    g_s[i] = g_styles[i] * msr;
}

// normalize weights, Winograd-transform to fp16 [comp][oc][ci], compute q
__global__ void k_wt(const float* __restrict__ cw) {
    int o = blockIdx.x, i = threadIdx.x;
    float g9[9]; float ss = 0.f;
    const float* p = cw + (o * CI + i) * 9;
    #pragma unroll
    for (int k = 0; k < 9; k++) { g9[k] = p[k]; ss += g9[k] * g9[k]; }
    __shared__ float red[512];
    red[i] = ss;
    __syncthreads();
    for (int s = 256; s; s >>= 1) { if (i < s) red[i] += red[i + s]; __syncthreads(); }
    float inv = rsqrtf(red[0] * (1.0f / 4608.0f));
    float g[3][3];
    #pragma unroll
    for (int k = 0; k < 9; k++) g[k / 3][k % 3] = g9[k] * inv;
    float r[4][3];
    #pragma unroll
    for (int j = 0; j < 3; j++) {
        r[0][j] = g[0][j];
        r[1][j] = 0.5f * (g[0][j] + g[1][j] + g[2][j]);
        r[2][j] = 0.5f * (g[0][j] - g[1][j] + g[2][j]);
        r[3][j] = g[2][j];
    }
    #pragma unroll
    for (int u = 0; u < 4; u++) {
        float gt0 = r[u][0];
        float gt1 = 0.5f * (r[u][0] + r[u][1] + r[u][2]);
        float gt2 = 0.5f * (r[u][0] - r[u][1] + r[u][2]);
        float gt3 = r[u][2];
        g_wt16[((u * 4 + 0) * 512 + o) * 512 + i] = __float2half_rn(gt0);
        g_wt16[((u * 4 + 1) * 512 + o) * 512 + i] = __float2half_rn(gt1);
        g_wt16[((u * 4 + 2) * 512 + o) * 512 + i] = __float2half_rn(gt2);
        g_wt16[((u * 4 + 3) * 512 + o) * 512 + i] = __float2half_rn(gt3);
    }
    g_q[o * CI + i] = ss * inv * inv;
}

// warp-per-(n,o) demod
__global__ void k_d() {
    int gw = blockIdx.x * 8 + (threadIdx.x >> 5);
    int lane = threadIdx.x & 31;
    int n = gw & 15, o = gw >> 4;
    const float* sp = g_s + n * CI;
    const float* qp = g_q + o * CI;
    float acc = 0.f;
    #pragma unroll 4
    for (int i = lane; i < 512; i += 32) { float sv = sp[i]; acc += sv * sv * qp[i]; }
    #pragma unroll
    for (int off = 16; off; off >>= 1) acc += __shfl_down_sync(0xffffffffu, acc, off);
    if (lane == 0) g_d[n * CO + o] = rsqrtf(acc + 1e-8f);
}

// ---------------- input transform: modulate, pad, B^T d B -> fp16 [n][comp][tile][ci]
#define XT_SMEM (4 * 68 * 65 * 4)
__global__ void __launch_bounds__(256, 2) k_xtrans(const float* __restrict__ x) {
    extern __shared__ float s[];   // [i 4][col 68][ci 64] stride 65
    int ty = blockIdx.x;   // 0..32
    int n  = blockIdx.y;
    int t  = threadIdx.x;
    const float* sp = g_s + n * 512;

    for (int ic0 = 0; ic0 < 512; ic0 += 64) {
        __syncthreads();
        for (int e = t; e < 4 * 68 * 64; e += 256) {
            int col = e % 68; int rest = e / 68;
            int i = rest & 3, ci = rest >> 2;
            int xr = 2 * ty + i - 2, xc = col - 2;
            float v = 0.f;
            if (xr >= 0 && xr < 64 && xc >= 0 && xc < 64)
                v = x[(((size_t)n * 512 + ic0 + ci) * 64 + xr) * 64 + xc] * sp[ic0 + ci];
            s[(i * 68 + col) * 65 + ci] = v;
        }
        __syncthreads();
        int ci = t & 63, txi = t >> 6;
        for (int pss = 0; pss < 9; pss++) {
            int tx = pss * 4 + txi;
            if (tx < 33) {
                float d[4][4];
                #pragma unroll
                for (int i = 0; i < 4; i++)
                    #pragma unroll
                    for (int j = 0; j < 4; j++)
                        d[i][j] = s[(i * 68 + 2 * tx + j) * 65 + ci];
                float tr[4][4];
                #pragma unroll
                for (int j = 0; j < 4; j++) {
                    tr[0][j] = d[0][j] - d[2][j];
                    tr[1][j] = d[1][j] + d[2][j];
                    tr[2][j] = d[2][j] - d[1][j];
                    tr[3][j] = d[1][j] - d[3][j];
                }
                int tile = ty * 33 + tx;
                #pragma unroll
                for (int u = 0; u < 4; u++) {
                    float d0 = tr[u][0] - tr[u][2];
                    float d1 = tr[u][1] + tr[u][2];
                    float d2 = tr[u][2] - tr[u][1];
                    float d3 = tr[u][1] - tr[u][3];
                    size_t b0 = ((size_t)((n * 16 + u * 4 + 0)) * NTP + tile) * 512 + ic0 + ci;
                    size_t b1 = ((size_t)((n * 16 + u * 4 + 1)) * NTP + tile) * 512 + ic0 + ci;
                    size_t b2 = ((size_t)((n * 16 + u * 4 + 2)) * NTP + tile) * 512 + ic0 + ci;
                    size_t b3 = ((size_t)((n * 16 + u * 4 + 3)) * NTP + tile) * 512 + ic0 + ci;
                    g_xt[b0] = __float2half_rn(d0);
                    g_xt[b1] = __float2half_rn(d1);
                    g_xt[b2] = __float2half_rn(d2);
                    g_xt[b3] = __float2half_rn(d3);
                }
            }
        }
    }
}

// ---------------- winograd GEMM: per comp, M[n][oc][comp][tile] fp32 ----------------
#define ROWB 144
#define TILEB 18432
#define STAGEB 36864
#define CONV_SMEM (2 * STAGEB)

__global__ void __launch_bounds__(256, 2) k_conv() {
    extern __shared__ char smem[];
    uint32_t sb = smem_u32(smem);
    int t = threadIdx.x, wid = t >> 5, lane = t & 31;
    int wm = wid & 1, wn = wid >> 1;
    int oc0 = blockIdx.x * 128;
    int t0  = blockIdx.y * 128;
    int n   = blockIdx.z;

    auto stage_issue = [&](int it, int buf) {
        int comp = it >> 3, ch = it & 7;
        int ic0 = ch << 6;
        const __half* ah = g_wt16 + ((size_t)(comp * 512 + oc0)) * 512 + ic0;
        const __half* bh = g_xt + ((size_t)(n * 16 + comp) * NTP + t0) * 512 + ic0;
        uint32_t sbase = sb + buf * STAGEB;
        #pragma unroll
        for (int j = 0; j < 8; j++) {
            int id = j * 256 + t;
            int tile = id >> 10, e = id & 1023;
            int row = e >> 3, c16 = e & 7;
            const __half* src = tile ? bh : ah;
            cp16(sbase + tile * TILEB + row * ROWB + c16 * 16,
                 src + (size_t)row * 512 + c16 * 8);
        }
        asm volatile("cp.async.commit_group;" ::: "memory");
    };

    stage_issue(0, 0);

    int rl = lane & 15, chh = lane >> 4;
    int g4 = lane >> 2, t4 = lane & 3;
    float* mbase = g_m + (((size_t)(n * 512 + oc0) * 16) * NTP + t0);

    for (int comp = 0; comp < 16; comp++) {
        float acc[4][4][4];
        #pragma unroll
        for (int mi = 0; mi < 4; mi++)
            #pragma unroll
            for (int ni = 0; ni < 4; ni++)
                #pragma unroll
                for (int q = 0; q < 4; q++) acc[mi][ni][q] = 0.f;

        #pragma unroll 1
        for (int ch = 0; ch < 8; ch++) {
            int it = comp * 8 + ch;
            int buf = it & 1;
            if (it + 1 < 128) {
                stage_issue(it + 1, buf ^ 1);
                asm volatile("cp.async.wait_group 1;" ::: "memory");
            } else {
                asm volatile("cp.async.wait_group 0;" ::: "memory");
            }
            __syncthreads();

            uint32_t At = sb + buf * STAGEB;
            uint32_t Bt = At + TILEB;
            #pragma unroll
            for (int kk = 0; kk < 4; kk++) {
                uint32_t kb = (kk * 2 + chh) * 16;
                uint32_t a[4][4], b[2][4];
                #pragma unroll
                for (int nj = 0; nj < 2; nj++)
                    ldsm4(b[nj], Bt + (wn * 32 + nj * 16 + rl) * ROWB + kb);
                #pragma unroll
                for (int mi = 0; mi < 4; mi++)
                    ldsm4(a[mi], At + (wm * 64 + mi * 16 + rl) * ROWB + kb);
                #pragma unroll
                for (int mi = 0; mi < 4; mi++)
                    #pragma unroll
                    for (int ni = 0; ni < 4; ni++) {
                        int nj = ni >> 1, sub = ni & 1;
                        mma16816(acc[mi][ni], a[mi], b[nj][sub], b[nj][sub + 2]);
                    }
            }
            __syncthreads();
        }

        float* mc = mbase + (size_t)comp * NTP;
        #pragma unroll
        for (int mi = 0; mi < 4; mi++) {
            int oa = wm * 64 + mi * 16 + g4;
            float* pa = mc + (size_t)oa * 16 * NTP;
            float* pb = mc + (size_t)(oa + 8) * 16 * NTP;
            #pragma unroll
            for (int ni = 0; ni < 4; ni++) {
                int px = wn * 32 + ni * 8 + t4 * 2;
                float2 va, vb;
                va.x = acc[mi][ni][0]; va.y = acc[mi][ni][1];
                vb.x = acc[mi][ni][2]; vb.y = acc[mi][ni][3];
                *(float2*)(pa + px) = va;
                *(float2*)(pb + px) = vb;
            }
        }
    }
}

// ---------------- fused output-transform + filtered_lrelu: one CTA per (n,oc) ----------------
// sY: 75 rows x 68 (rows 0-3 and 70-74 zero; rows 4..69 = y rows 0..65)
// sUV: 138 rows x stride 77 (cols 0-3, 70-73 zero pad; col 74 garbage-unused)
// sU: 42 x 139; sDV: 16 x 139
#define F_SY 0
#define F_SUV 5100
#define F_SU 15726
#define F_SDV 21564
#define FIR_SMEM (23788 * 4)
#define LRC1 5.656854249492381f
#define LRC2 1.1313708498984762f

__global__ void __launch_bounds__(256, 2) k_fir(const float* __restrict__ fu,
                                                const float* __restrict__ fd,
                                                const float* __restrict__ cb,
                                                float* __restrict__ out) {
    extern __shared__ float sm[];
    float* sY  = sm + F_SY;
    float* sUV = sm + F_SUV;
    float* sU  = sm + F_SU;
    float* sDV = sm + F_SDV;
    int t = threadIdx.x;
    int nc = blockIdx.x;            // n*512 + oc
    int oc = nc & 511;

    float fe[6], fo[6], fdr[12];
    #pragma unroll
    for (int j = 0; j < 6; j++) { fe[j] = fu[2 * j]; fo[j] = fu[2 * j + 1]; }
    #pragma unroll
    for (int j = 0; j < 12; j++) fdr[j] = fd[j];

    float4* sY4 = (float4*)sY;
    float4 z4 = make_float4(0.f, 0.f, 0.f, 0.f);
    for (int e = t; e < 1275; e += 256) sY4[e] = z4;   // 75*68/4
    for (int e = t; e < 138 * 8; e += 256) {
        int r = e >> 3, c = e & 7;
        sUV[r * 77 + ((c < 4) ? c : (66 + c))] = 0.f;
    }
    __syncthreads();

    // output transform from fp32 m: m[16] -> 2x2 pixels, demod + bias
    {
        const float* mb = g_m + ((size_t)nc * 16) * NTP;
        float dd = g_d[nc];
        float bias = cb[oc];
        for (int tile = t; tile < NT; tile += 256) {
            float m[16];
            #pragma unroll
            for (int c = 0; c < 16; c++) m[c] = mb[(size_t)c * NTP + tile];
            float s0[4], s1[4];
            #pragma unroll
            for (int v = 0; v < 4; v++) {
                s0[v] = m[v] + m[4 + v] + m[8 + v];
                s1[v] = m[4 + v] - m[8 + v] - m[12 + v];
            }
            float y00 = s0[0] + s0[1] + s0[2], y01 = s0[1] - s0[2] - s0[3];
            float y10 = s1[0] + s1[1] + s1[2], y11 = s1[1] - s1[2] - s1[3];
            int ty = tile / 33, tx = tile - ty * 33;
            int off = (4 + 2 * ty) * 68 + 2 * tx;
            sY[off]      = y00 * dd + bias;
            sY[off + 1]  = y01 * dd + bias;
            sY[off + 68] = y10 * dd + bias;
            sY[off + 69] = y11 * dd + bias;
        }
    }
    __syncthreads();

    // up-vertical, 2-pair blocked: 7 loads -> 4 output rows (4g..4g+3)
    for (int e = t; e < 35 * 66; e += 256) {
        int g = e / 66, xx = e - g * 66;
        const float* src = sY + (2 * g) * 68 + xx;
        float r[7];
        #pragma unroll
        for (int j = 0; j < 7; j++) r[j] = src[j * 68];
        float v0 = 0.f, v1 = 0.f, v2 = 0.f, v3 = 0.f;
        #pragma unroll
        for (int j = 0; j < 6; j++) {
            v0 += fo[j] * r[j];
            v1 += fe[j] * r[j];
            v2 += fo[j] * r[j + 1];
            v3 += fe[j] * r[j + 1];
        }
        float* dst = sUV + (4 * g) * 77 + 4 + xx;
        dst[0] = v0;
        dst[77] = v1;
        if (g < 34) { dst[154] = v2; dst[231] = v3; }
    }
    __syncthreads();

    for (int oy0 = 0; oy0 < 64; oy0 += 16) {
        // up-horizontal + lrelu + clamp, 2-pair blocked: 7 loads -> 4 output cols
        // item order: rr fast within warp (conflict-free with stride 77)
        for (int e = t; e < 35 * 42; e += 256) {
            int g = e / 42, rr = e - g * 42;
            const float* src = sUV + (2 * oy0 + rr) * 77 + 2 * g;
            float r[7];
            #pragma unroll
            for (int j = 0; j < 7; j++) r[j] = src[j];
            float v0 = 0.f, v1 = 0.f, v2 = 0.f, v3 = 0.f;
            #pragma unroll
            for (int j = 0; j < 6; j++) {
                v0 += fo[j] * r[j];
                v1 += fe[j] * r[j];
                v2 += fo[j] * r[j + 1];
                v3 += fe[j] * r[j + 1];
            }
            float w0 = fminf(fmaxf(fmaxf(v0 * LRC1, v0 * LRC2), -256.f), 256.f);
            float w1 = fminf(fmaxf(fmaxf(v1 * LRC1, v1 * LRC2), -256.f), 256.f);
            float* dst = sU + rr * 139 + 4 * g;
            dst[0] = w0;
            dst[1] = w1;
            if (g < 34) {
                float w2 = fminf(fmaxf(fmaxf(v2 * LRC1, v2 * LRC2), -256.f), 256.f);
                float w3 = fminf(fmaxf(fmaxf(v3 * LRC1, v3 * LRC2), -256.f), 256.f);
                dst[2] = w2;
                dst[3] = w3;
            }
        }
        __syncthreads();
        // down-vertical, 4-way register-blocked (18 loads -> 4 outputs)
        for (int e = t; e < 4 * 138; e += 256) {
            int c = e % 138, g = e / 138;
            const float* src = sU + (8 * g) * 139 + c;
            float r[18];
            #pragma unroll
            for (int j = 0; j < 18; j++) r[j] = src[j * 139];
            #pragma unroll
            for (int j = 0; j < 4; j++) {
                float acc = 0.f;
                #pragma unroll
                for (int tp = 0; tp < 12; tp++) acc += fdr[tp] * r[2 * j + tp];
                sDV[(4 * g + j) * 139 + c] = acc;
            }
        }
        __syncthreads();
        // down-horizontal, 4-way register-blocked -> float4 out
        {
            int yy = t & 15, oxg = t >> 4;   // 256 items exactly
            const float* src = sDV + yy * 139 + 8 * oxg;
            float r[18];
            #pragma unroll
            for (int j = 0; j < 18; j++) r[j] = src[j];
            float4 o4;
            float* op = (float*)&o4;
            #pragma unroll
            for (int j = 0; j < 4; j++) {
                float acc = 0.f;
                #pragma unroll
                for (int tp = 0; tp < 12; tp++) acc += fdr[tp] * r[2 * j + tp];
                op[j] = acc;
            }
            *(float4*)(out + (size_t)nc * 4096 + (oy0 + yy) * 64 + 4 * oxg) = o4;
        }
        __syncthreads();
    }
}

// ---------------- launch ----------------
extern "C" void kernel_launch(void* const* d_in, const int* in_sizes, int n_in,
                              void* d_out, int out_size) {
    const float* x  = (const float*)d_in[0];
    const float* w  = (const float*)d_in[1];
    const float* aw = (const float*)d_in[2];
    const float* ab = (const float*)d_in[3];
    const float* cw = (const float*)d_in[4];
    const float* cb = (const float*)d_in[5];
    const float* fu = (const float*)d_in[6];
    const float* fd = (const float*)d_in[7];
    float* out = (float*)d_out;

    cudaFuncSetAttribute(k_conv,   cudaFuncAttributeMaxDynamicSharedMemorySize, CONV_SMEM);
    cudaFuncSetAttribute(k_fir,    cudaFuncAttributeMaxDynamicSharedMemorySize, FIR_SMEM);
    cudaFuncSetAttribute(k_xtrans, cudaFuncAttributeMaxDynamicSharedMemorySize, XT_SMEM);

    k_styles<<<NB, 512>>>(w, aw, ab);
    k_norm_s<<<NB, 512>>>();
    k_wt<<<CO, 512>>>(cw);
    k_d<<<1024, 256>>>();
    k_xtrans<<<dim3(33, NB), 256, XT_SMEM>>>(x);

    k_conv<<<dim3(4, 9, NB), 256, CONV_SMEM>>>();

    k_fir<<<NB * CO, 256, FIR_SMEM>>>(fu, fd, cb, out);
}